// round 10
// baseline (speedup 1.0000x reference)
#include <cuda_runtime.h>
#include <math.h>

#define EPSF 1e-5f

// Re-laid-out weights: Wt4[B][g][C] (float4), g = jk/4.
// Wt4[B*128 + g*32 + C] = { W[B][C][4g..4g+3] }
__device__ float4 Wt4_buf[288 * 4 * 32];

__global__ void transpose_W_kernel(const float* __restrict__ Wg) {
    int idx = blockIdx.x * 256 + threadIdx.x;
    if (idx >= 288 * 16 * 32) return;
    int q = idx & 3;
    int C = (idx >> 2) & 31;
    int g = (idx >> 7) & 3;
    int B = idx >> 9;
    ((float*)Wt4_buf)[idx] = Wg[((B << 5) + C) * 16 + (g << 2) + q];
}

typedef unsigned long long u64;

// packed f32x2 helpers
#define PACK2(d, s)      asm("mov.b64 %0, {%1, %1};" : "=l"(d) : "f"(s))
#define UNPK2(lo, hi, s) asm("mov.b64 {%0, %1}, %2;" : "=f"(lo), "=f"(hi) : "l"(s))
#define FMA2(d, a, b, c) asm("fma.rn.f32x2 %0, %1, %2, %3;" : "=l"(d) : "l"(a), "l"(b), "l"(c))
#define MUL2(d, a, b)    asm("mul.rn.f32x2 %0, %1, %2;" : "=l"(d) : "l"(a), "l"(b))
#define ADD2(d, a, b)    asm("add.rn.f32x2 %0, %1, %2;" : "=l"(d) : "l"(a), "l"(b))

__device__ __forceinline__ float warp_sum(float v) {
    #pragma unroll
    for (int o = 16; o > 0; o >>= 1)
        v += __shfl_xor_sync(0xffffffffu, v, o);
    return v;
}

// SMEM layout (floats):
//  Xs   [288*16]        = 4608  @0
//  Wst  [8w][2s][512]   = 8192  @4608     (per-warp double-buffered W stage)
//  vbuf [8*32*16]       = 4096  @12800
//  vcur [32*16]         = 512   @16896
//  invd [32]            = 32    @17408
//  mred [8*32]          = 256   @17440
//  nred [8*32]          = 256   @17696
#define SMEM_FLOATS 17952
#define WST_OFF 4608

// p_out has 4*32*16*8*8 = 131072 elements; a_out follows it.
#define AOUT_BASE 131072

// Stage W[B] (this lane's 64 bytes) into smem slot via cp.async.cg.
// Each lane stages exactly the bytes it later reads -> per-thread pipeline.
#define STAGE(B, slot)                                                         \
    {                                                                          \
        unsigned d_ = wstS + (slot) * 2048 + (lane << 4);                      \
        const float4* s_ = Wt4_buf + ((B) << 7) + lane;                        \
        asm volatile("cp.async.cg.shared.global [%0], [%1], 16;" ::"r"(d_),        "l"(s_));      \
        asm volatile("cp.async.cg.shared.global [%0], [%1], 16;" ::"r"(d_ + 512),  "l"(s_ + 32)); \
        asm volatile("cp.async.cg.shared.global [%0], [%1], 16;" ::"r"(d_ + 1024), "l"(s_ + 64)); \
        asm volatile("cp.async.cg.shared.global [%0], [%1], 16;" ::"r"(d_ + 1536), "l"(s_ + 96)); \
        asm volatile("cp.async.commit_group;");                                \
    }

#define LOADW_S(slot, wa0, wb0, wa1, wb1, wa2, wb2, wa3, wb3)                  \
    {                                                                          \
        const ulonglong2* p_ = reinterpret_cast<const ulonglong2*>(            \
            Wst + (wp << 10) + ((slot) << 9)) + lane;                          \
        ulonglong2 t0 = p_[0], t1 = p_[32], t2 = p_[64], t3 = p_[96];          \
        wa0 = t0.x; wb0 = t0.y; wa1 = t1.x; wb1 = t1.y;                        \
        wa2 = t2.x; wb2 = t2.y; wa3 = t3.x; wb3 = t3.y;                        \
    }

// u[16] = X[B] (4x4) @ W (packed regs). 8 packed u64 results.
#define COMPUTE_U_P(B, wa0, wb0, wa1, wb1, wa2, wb2, wa3, wb3,                 \
                    ua0, ub0, ua1, ub1, ua2, ub2, ua3, ub3)                    \
    {                                                                          \
        const float4* Xp = Xv + ((B) << 2);                                    \
        float4 xr0 = Xp[0], xr1 = Xp[1], xr2 = Xp[2], xr3 = Xp[3];             \
        u64 xp0, xp1, xp2, xp3;                                                \
        PACK2(xp0, xr0.x); PACK2(xp1, xr0.y); PACK2(xp2, xr0.z); PACK2(xp3, xr0.w); \
        MUL2(ua0, xp0, wa0); MUL2(ub0, xp0, wb0);                              \
        FMA2(ua0, xp1, wa1, ua0); FMA2(ub0, xp1, wb1, ub0);                    \
        FMA2(ua0, xp2, wa2, ua0); FMA2(ub0, xp2, wb2, ub0);                    \
        FMA2(ua0, xp3, wa3, ua0); FMA2(ub0, xp3, wb3, ub0);                    \
        PACK2(xp0, xr1.x); PACK2(xp1, xr1.y); PACK2(xp2, xr1.z); PACK2(xp3, xr1.w); \
        MUL2(ua1, xp0, wa0); MUL2(ub1, xp0, wb0);                              \
        FMA2(ua1, xp1, wa1, ua1); FMA2(ub1, xp1, wb1, ub1);                    \
        FMA2(ua1, xp2, wa2, ua1); FMA2(ub1, xp2, wb2, ub1);                    \
        FMA2(ua1, xp3, wa3, ua1); FMA2(ub1, xp3, wb3, ub1);                    \
        PACK2(xp0, xr2.x); PACK2(xp1, xr2.y); PACK2(xp2, xr2.z); PACK2(xp3, xr2.w); \
        MUL2(ua2, xp0, wa0); MUL2(ub2, xp0, wb0);                              \
        FMA2(ua2, xp1, wa1, ua2); FMA2(ub2, xp1, wb1, ub2);                    \
        FMA2(ua2, xp2, wa2, ua2); FMA2(ub2, xp2, wb2, ub2);                    \
        FMA2(ua2, xp3, wa3, ua2); FMA2(ub2, xp3, wb3, ub2);                    \
        PACK2(xp0, xr3.x); PACK2(xp1, xr3.y); PACK2(xp2, xr3.z); PACK2(xp3, xr3.w); \
        MUL2(ua3, xp0, wa0); MUL2(ub3, xp0, wb0);                              \
        FMA2(ua3, xp1, wa1, ua3); FMA2(ub3, xp1, wb1, ub3);                    \
        FMA2(ua3, xp2, wa2, ua3); FMA2(ub3, xp2, wb2, ub3);                    \
        FMA2(ua3, xp3, wa3, ua3); FMA2(ub3, xp3, wb3, ub3);                    \
    }

// packed elementwise dot of 8 pairs -> scalar (lo+hi)
#define PDOT8(res, ua0, ub0, ua1, ub1, ua2, ub2, ua3, ub3,                     \
              va0, vb0, va1, vb1, va2, vb2, va3, vb3)                          \
    {                                                                          \
        u64 t_;                                                                \
        MUL2(t_, ua0, va0); FMA2(t_, ub0, vb0, t_);                            \
        FMA2(t_, ua1, va1, t_); FMA2(t_, ub1, vb1, t_);                        \
        FMA2(t_, ua2, va2, t_); FMA2(t_, ub2, vb2, t_);                        \
        FMA2(t_, ua3, va3, t_); FMA2(t_, ub3, vb3, t_);                        \
        float lo_, hi_;                                                        \
        UNPK2(lo_, hi_, t_);                                                   \
        res = lo_ + hi_;                                                       \
    }

__global__ __launch_bounds__(256, 2)
void convcaps_kernel(const float* __restrict__ x,
                     float* __restrict__ out) {
    extern __shared__ float smem[];
    float* Xs   = smem;
    float* Wst  = smem + WST_OFF;
    float* vbuf = smem + 12800;
    float* vcur = smem + 16896;
    float* invd = smem + 17408;
    float* mred = smem + 17440;
    float* nred = smem + 17696;

    const int tid  = threadIdx.x;
    const int lane = tid & 31;     // = C
    const int wp   = tid >> 5;     // warp id, B ≡ wp (mod 8)
    const int pos  = blockIdx.x;   // b*64 + h*8 + w
    const int b    = pos >> 6;
    const int hw   = pos & 63;
    const int h    = hw >> 3;
    const int w    = hw & 7;

    const unsigned wstS =
        (unsigned)__cvta_generic_to_shared(smem) + WST_OFF * 4 + (wp << 12);

    // ---- gather patch poses X[B_=Bcap*9+ki*3+kj][ps] with zero padding ----
    for (int idx = tid; idx < 4608; idx += 256) {
        int B_ = idx >> 4, p = idx & 15;
        int Bcap = B_ / 9;
        int kk = B_ - Bcap * 9;
        int ki = kk / 3, kj = kk - ki * 3;
        int hh = 2 * h + ki - 1, ww = 2 * w + kj - 1;
        float val = 0.f;
        if ((unsigned)hh < 16u && (unsigned)ww < 16u)
            val = x[(((b * 32 + Bcap) * 16 + p) << 8) + (hh << 4) + ww];
        Xs[idx] = val;
    }
    __syncthreads();

    const float4* Xv     = reinterpret_cast<const float4*>(Xs);
    float4*       vbufv  = reinterpret_cast<float4*>(vbuf);
    float4*       vcurv  = reinterpret_cast<float4*>(vcur);
    ulonglong2*   vbufp  = reinterpret_cast<ulonglong2*>(vbuf);
    const ulonglong2* vcurp = reinterpret_cast<const ulonglong2*>(vcur);

    u64 aa0, ab0, aa1, ab1, aa2, ab2, aa3, ab3;

    // ================= PASS A: norms (for max-min) + uniform sum ==========
    {
        float mx = -3.4e38f, mn = 3.4e38f;
        u64 z = 0;
        aa0 = ab0 = aa1 = ab1 = aa2 = ab2 = aa3 = ab3 = z;
        STAGE(wp, 0)
        #pragma unroll 2
        for (int k = 0; k < 36; k++) {
            int Bn = wp + ((k < 35) ? ((k + 1) << 3) : 0);
            STAGE(Bn, (k + 1) & 1)
            asm volatile("cp.async.wait_group 1;");
            u64 wa0, wb0, wa1, wb1, wa2, wb2, wa3, wb3;
            LOADW_S(k & 1, wa0, wb0, wa1, wb1, wa2, wb2, wa3, wb3)
            int B = wp + (k << 3);
            u64 ua0, ub0, ua1, ub1, ua2, ub2, ua3, ub3;
            COMPUTE_U_P(B, wa0, wb0, wa1, wb1, wa2, wb2, wa3, wb3,
                           ua0, ub0, ua1, ub1, ua2, ub2, ua3, ub3)
            float ss;
            PDOT8(ss, ua0, ub0, ua1, ub1, ua2, ub2, ua3, ub3,
                      ua0, ub0, ua1, ub1, ua2, ub2, ua3, ub3)
            float nrm = __fsqrt_rn(ss + EPSF);
            mx = fmaxf(mx, nrm);
            mn = fminf(mn, nrm);
            ADD2(aa0, aa0, ua0); ADD2(ab0, ab0, ub0);
            ADD2(aa1, aa1, ua1); ADD2(ab1, ab1, ub1);
            ADD2(aa2, aa2, ua2); ADD2(ab2, ab2, ub2);
            ADD2(aa3, aa3, ua3); ADD2(ab3, ab3, ub3);
        }
        asm volatile("cp.async.wait_group 0;");
        mred[(wp << 5) + lane] = mx;
        nred[(wp << 5) + lane] = mn;
        int base = ((wp << 5) + lane) << 2;
        ulonglong2 s0; s0.x = aa0; s0.y = ab0; vbufp[base + 0] = s0;
        ulonglong2 s1; s1.x = aa1; s1.y = ab1; vbufp[base + 1] = s1;
        ulonglong2 s2; s2.x = aa2; s2.y = ab2; vbufp[base + 2] = s2;
        ulonglong2 s3; s3.x = aa3; s3.y = ab3; vbufp[base + 3] = s3;
    }
    __syncthreads();
    if (tid < 32) {
        float M = -3.4e38f, m = 3.4e38f;
        #pragma unroll
        for (int k = 0; k < 8; k++) {
            M = fmaxf(M, mred[(k << 5) + tid]);
            m = fminf(m, nred[(k << 5) + tid]);
        }
        invd[tid] = 1.f / (M - m);
    }
    __syncthreads();
    // reduce across warps + squash -> v0
    if (tid < 128) {
        int C = tid >> 2;
        float4 acc = vbufv[tid];
        #pragma unroll
        for (int k = 1; k < 8; k++) {
            float4 t = vbufv[(k << 7) + tid];
            acc.x += t.x; acc.y += t.y; acc.z += t.z; acc.w += t.w;
        }
        float f = invd[C] * (1.f / 32.f);
        acc.x *= f; acc.y *= f; acc.z *= f; acc.w *= f;
        float s = acc.x * acc.x + acc.y * acc.y + acc.z * acc.z + acc.w * acc.w;
        s += __shfl_xor_sync(0xffffffffu, s, 1);
        s += __shfl_xor_sync(0xffffffffu, s, 2);
        float nrm = __fsqrt_rn(s + EPSF);
        float g = 1.f / (1.f + nrm);
        acc.x *= g; acc.y *= g; acc.z *= g; acc.w *= g;
        vcurv[tid] = acc;
    }
    __syncthreads();

    const float invd_c = invd[lane];

    // v0 packed, kept in registers (pass C uses v0+v1 by linearity)
    u64 va0, vb0, va1, vb1, va2, vb2, va3, vb3;
    {
        ulonglong2 t0 = vcurp[(lane << 2) + 0];
        ulonglong2 t1 = vcurp[(lane << 2) + 1];
        ulonglong2 t2 = vcurp[(lane << 2) + 2];
        ulonglong2 t3 = vcurp[(lane << 2) + 3];
        va0 = t0.x; vb0 = t0.y; va1 = t1.x; vb1 = t1.y;
        va2 = t2.x; vb2 = t2.y; va3 = t3.x; vb3 = t3.y;
    }

    // ================= PASS B: r1 = u.v0, c1 = softmax_C, accum c1*u ======
    {
        u64 z = 0;
        aa0 = ab0 = aa1 = ab1 = aa2 = ab2 = aa3 = ab3 = z;
        STAGE(wp, 0)
        #pragma unroll 2
        for (int k = 0; k < 36; k++) {
            int Bn = wp + ((k < 35) ? ((k + 1) << 3) : 0);
            STAGE(Bn, (k + 1) & 1)
            asm volatile("cp.async.wait_group 1;");
            u64 wa0, wb0, wa1, wb1, wa2, wb2, wa3, wb3;
            LOADW_S(k & 1, wa0, wb0, wa1, wb1, wa2, wb2, wa3, wb3)
            int B = wp + (k << 3);
            u64 ua0, ub0, ua1, ub1, ua2, ub2, ua3, ub3;
            COMPUTE_U_P(B, wa0, wb0, wa1, wb1, wa2, wb2, wa3, wb3,
                           ua0, ub0, ua1, ub1, ua2, ub2, ua3, ub3)
            float dt;
            PDOT8(dt, ua0, ub0, ua1, ub1, ua2, ub2, ua3, ub3,
                      va0, vb0, va1, vb1, va2, vb2, va3, vb3)
            float r = dt * invd_c;
            float e = __expf(r);
            float s = warp_sum(e);
            float c = __fdividef(e, s);
            u64 cP; PACK2(cP, c);
            FMA2(aa0, cP, ua0, aa0); FMA2(ab0, cP, ub0, ab0);
            FMA2(aa1, cP, ua1, aa1); FMA2(ab1, cP, ub1, ab1);
            FMA2(aa2, cP, ua2, aa2); FMA2(ab2, cP, ub2, ab2);
            FMA2(aa3, cP, ua3, aa3); FMA2(ab3, cP, ub3, ab3);
        }
        asm volatile("cp.async.wait_group 0;");
        int base = ((wp << 5) + lane) << 2;
        ulonglong2 s0; s0.x = aa0; s0.y = ab0; vbufp[base + 0] = s0;
        ulonglong2 s1; s1.x = aa1; s1.y = ab1; vbufp[base + 1] = s1;
        ulonglong2 s2; s2.x = aa2; s2.y = ab2; vbufp[base + 2] = s2;
        ulonglong2 s3; s3.x = aa3; s3.y = ab3; vbufp[base + 3] = s3;
    }
    __syncthreads();
    if (tid < 128) {
        int C = tid >> 2;
        float4 acc = vbufv[tid];
        #pragma unroll
        for (int k = 1; k < 8; k++) {
            float4 t = vbufv[(k << 7) + tid];
            acc.x += t.x; acc.y += t.y; acc.z += t.z; acc.w += t.w;
        }
        float f = invd[C];
        acc.x *= f; acc.y *= f; acc.z *= f; acc.w *= f;
        float s = acc.x * acc.x + acc.y * acc.y + acc.z * acc.z + acc.w * acc.w;
        s += __shfl_xor_sync(0xffffffffu, s, 1);
        s += __shfl_xor_sync(0xffffffffu, s, 2);
        float nrm = __fsqrt_rn(s + EPSF);
        float g = 1.f / (1.f + nrm);
        acc.x *= g; acc.y *= g; acc.z *= g; acc.w *= g;
        vcurv[tid] = acc;   // v1
    }
    __syncthreads();

    // vl = v0 + v1 (linearity: r2 = r1 + u.v1*invd = invd * u.(v0+v1))
    {
        ulonglong2 t0 = vcurp[(lane << 2) + 0];
        ulonglong2 t1 = vcurp[(lane << 2) + 1];
        ulonglong2 t2 = vcurp[(lane << 2) + 2];
        ulonglong2 t3 = vcurp[(lane << 2) + 3];
        ADD2(va0, va0, t0.x); ADD2(vb0, vb0, t0.y);
        ADD2(va1, va1, t1.x); ADD2(vb1, vb1, t1.y);
        ADD2(va2, va2, t2.x); ADD2(vb2, vb2, t2.y);
        ADD2(va3, va3, t3.x); ADD2(vb3, vb3, t3.y);
    }

    // ================= PASS C: r2 = invd*u.(v0+v1), c2, accum, output ======
    {
        u64 z = 0;
        aa0 = ab0 = aa1 = ab1 = aa2 = ab2 = aa3 = ab3 = z;
        STAGE(wp, 0)
        #pragma unroll 2
        for (int k = 0; k < 36; k++) {
            int Bn = wp + ((k < 35) ? ((k + 1) << 3) : 0);
            STAGE(Bn, (k + 1) & 1)
            asm volatile("cp.async.wait_group 1;");
            u64 wa0, wb0, wa1, wb1, wa2, wb2, wa3, wb3;
            LOADW_S(k & 1, wa0, wb0, wa1, wb1, wa2, wb2, wa3, wb3)
            int B = wp + (k << 3);
            u64 ua0, ub0, ua1, ub1, ua2, ub2, ua3, ub3;
            COMPUTE_U_P(B, wa0, wb0, wa1, wb1, wa2, wb2, wa3, wb3,
                           ua0, ub0, ua1, ub1, ua2, ub2, ua3, ub3)
            float dt;
            PDOT8(dt, ua0, ub0, ua1, ub1, ua2, ub2, ua3, ub3,
                      va0, vb0, va1, vb1, va2, vb2, va3, vb3)
            float r = dt * invd_c;
            float e = __expf(r);
            float s = warp_sum(e);
            float c = __fdividef(e, s);
            u64 cP; PACK2(cP, c);
            FMA2(aa0, cP, ua0, aa0); FMA2(ab0, cP, ub0, ab0);
            FMA2(aa1, cP, ua1, aa1); FMA2(ab1, cP, ub1, ab1);
            FMA2(aa2, cP, ua2, aa2); FMA2(ab2, cP, ub2, ab2);
            FMA2(aa3, cP, ua3, aa3); FMA2(ab3, cP, ub3, ab3);
        }
        asm volatile("cp.async.wait_group 0;");
        int base = ((wp << 5) + lane) << 2;
        ulonglong2 s0; s0.x = aa0; s0.y = ab0; vbufp[base + 0] = s0;
        ulonglong2 s1; s1.x = aa1; s1.y = ab1; vbufp[base + 1] = s1;
        ulonglong2 s2; s2.x = aa2; s2.y = ab2; vbufp[base + 2] = s2;
        ulonglong2 s3; s3.x = aa3; s3.y = ab3; vbufp[base + 3] = s3;
    }
    __syncthreads();
    if (tid < 128) {
        int C = tid >> 2, q = tid & 3;
        float4 acc = vbufv[tid];
        #pragma unroll
        for (int k = 1; k < 8; k++) {
            float4 t = vbufv[(k << 7) + tid];
            acc.x += t.x; acc.y += t.y; acc.z += t.z; acc.w += t.w;
        }
        float f = invd[C];
        acc.x *= f; acc.y *= f; acc.z *= f; acc.w *= f;
        float s = acc.x * acc.x + acc.y * acc.y + acc.z * acc.z + acc.w * acc.w;
        s += __shfl_xor_sync(0xffffffffu, s, 1);
        s += __shfl_xor_sync(0xffffffffu, s, 2);
        float nrm = __fsqrt_rn(s + EPSF);
        float g = 1.f / (1.f + nrm);
        acc.x *= g; acc.y *= g; acc.z *= g; acc.w *= g;   // v2 (p_out)
        float s2 = acc.x * acc.x + acc.y * acc.y + acc.z * acc.z + acc.w * acc.w;
        s2 += __shfl_xor_sync(0xffffffffu, s2, 1);
        s2 += __shfl_xor_sync(0xffffffffu, s2, 2);
        float aout = __fsqrt_rn(s2 + EPSF);               // a_out = safe_norm(v2)
        int basep = (((b * 32 + C) * 16 + (q << 2)) << 6) + hw;
        out[basep]       = acc.x;
        out[basep + 64]  = acc.y;
        out[basep + 128] = acc.z;
        out[basep + 192] = acc.w;
        if (q == 0)
            out[AOUT_BASE + ((b * 32 + C) << 6) + hw] = aout;
    }
}

extern "C" void kernel_launch(void* const* d_in, const int* in_sizes, int n_in,
                              void* d_out, int out_size) {
    (void)out_size;
    // Resolve inputs BY SIZE — immune to metadata ordering.
    const float* x  = nullptr;
    const float* Wg = nullptr;
    for (int i = 0; i < n_in; i++) {
        if (in_sizes[i] == 524288)      x  = (const float*)d_in[i];
        else if (in_sizes[i] == 147456) Wg = (const float*)d_in[i];
    }
    float* out = (float*)d_out;

    transpose_W_kernel<<<(288 * 16 * 32 + 255) / 256, 256>>>(Wg);

    const size_t smem_bytes = SMEM_FLOATS * sizeof(float);
    cudaFuncSetAttribute(convcaps_kernel,
                         cudaFuncAttributeMaxDynamicSharedMemorySize,
                         (int)smem_bytes);
    convcaps_kernel<<<256, 256, smem_bytes>>>(x, out);
}

// round 11
// speedup vs baseline: 1.0351x; 1.0351x over previous
#include <cuda_runtime.h>
#include <math.h>

#define EPSF 1e-5f

// Re-laid-out weights: Wt4[B][g][C] (float4), g = jk/4.
__device__ float4 Wt4_buf[288 * 4 * 32];

__global__ void transpose_W_kernel(const float* __restrict__ Wg) {
    int idx = blockIdx.x * 256 + threadIdx.x;
    if (idx >= 288 * 16 * 32) return;
    int q = idx & 3;
    int C = (idx >> 2) & 31;
    int g = (idx >> 7) & 3;
    int B = idx >> 9;
    ((float*)Wt4_buf)[idx] = Wg[((B << 5) + C) * 16 + (g << 2) + q];
}

typedef unsigned long long u64;

// packed f32x2 helpers
#define PACK2(d, s)      asm("mov.b64 %0, {%1, %1};" : "=l"(d) : "f"(s))
#define UNPK2(lo, hi, s) asm("mov.b64 {%0, %1}, %2;" : "=f"(lo), "=f"(hi) : "l"(s))
#define FMA2(d, a, b, c) asm("fma.rn.f32x2 %0, %1, %2, %3;" : "=l"(d) : "l"(a), "l"(b), "l"(c))
#define MUL2(d, a, b)    asm("mul.rn.f32x2 %0, %1, %2;" : "=l"(d) : "l"(a), "l"(b))
#define ADD2(d, a, b)    asm("add.rn.f32x2 %0, %1, %2;" : "=l"(d) : "l"(a), "l"(b))

// SMEM layout (floats):
//  Xs   [288*16]      = 4608   @0
//  vbuf [8*32*16]     = 4096   @4608
//  vcur [32*16]       = 512    @8704
//  invd [32]          = 32     @9216
//  mred [8*32]        = 256    @9248
//  nred [8*32]        = 256    @9504
#define SMEM_FLOATS 9760

// p_out has 4*32*16*8*8 = 131072 elements; a_out follows it.
#define AOUT_BASE 131072

#define LOADW(B, wa0, wb0, wa1, wb1, wa2, wb2, wa3, wb3)                       \
    {                                                                          \
        const ulonglong2* Wp_ =                                                \
            reinterpret_cast<const ulonglong2*>(Wt4_buf) + ((B) << 7) + lane;  \
        ulonglong2 t0 = Wp_[0], t1 = Wp_[32], t2 = Wp_[64], t3 = Wp_[96];      \
        wa0 = t0.x; wb0 = t0.y; wa1 = t1.x; wb1 = t1.y;                        \
        wa2 = t2.x; wb2 = t2.y; wa3 = t3.x; wb3 = t3.y;                        \
    }

// u[16] = X[B] (4x4) @ W (packed regs). 8 packed u64 results.
#define COMPUTE_U_P(B, wa0, wb0, wa1, wb1, wa2, wb2, wa3, wb3,                 \
                    ua0, ub0, ua1, ub1, ua2, ub2, ua3, ub3)                    \
    {                                                                          \
        const float4* Xp = Xv + ((B) << 2);                                    \
        float4 xr0 = Xp[0], xr1 = Xp[1], xr2 = Xp[2], xr3 = Xp[3];             \
        u64 xp0, xp1, xp2, xp3;                                                \
        PACK2(xp0, xr0.x); PACK2(xp1, xr0.y); PACK2(xp2, xr0.z); PACK2(xp3, xr0.w); \
        MUL2(ua0, xp0, wa0); MUL2(ub0, xp0, wb0);                              \
        FMA2(ua0, xp1, wa1, ua0); FMA2(ub0, xp1, wb1, ub0);                    \
        FMA2(ua0, xp2, wa2, ua0); FMA2(ub0, xp2, wb2, ub0);                    \
        FMA2(ua0, xp3, wa3, ua0); FMA2(ub0, xp3, wb3, ub0);                    \
        PACK2(xp0, xr1.x); PACK2(xp1, xr1.y); PACK2(xp2, xr1.z); PACK2(xp3, xr1.w); \
        MUL2(ua1, xp0, wa0); MUL2(ub1, xp0, wb0);                              \
        FMA2(ua1, xp1, wa1, ua1); FMA2(ub1, xp1, wb1, ub1);                    \
        FMA2(ua1, xp2, wa2, ua1); FMA2(ub1, xp2, wb2, ub1);                    \
        FMA2(ua1, xp3, wa3, ua1); FMA2(ub1, xp3, wb3, ub1);                    \
        PACK2(xp0, xr2.x); PACK2(xp1, xr2.y); PACK2(xp2, xr2.z); PACK2(xp3, xr2.w); \
        MUL2(ua2, xp0, wa0); MUL2(ub2, xp0, wb0);                              \
        FMA2(ua2, xp1, wa1, ua2); FMA2(ub2, xp1, wb1, ub2);                    \
        FMA2(ua2, xp2, wa2, ua2); FMA2(ub2, xp2, wb2, ub2);                    \
        FMA2(ua2, xp3, wa3, ua2); FMA2(ub2, xp3, wb3, ub2);                    \
        PACK2(xp0, xr3.x); PACK2(xp1, xr3.y); PACK2(xp2, xr3.z); PACK2(xp3, xr3.w); \
        MUL2(ua3, xp0, wa0); MUL2(ub3, xp0, wb0);                              \
        FMA2(ua3, xp1, wa1, ua3); FMA2(ub3, xp1, wb1, ub3);                    \
        FMA2(ua3, xp2, wa2, ua3); FMA2(ub3, xp2, wb2, ub3);                    \
        FMA2(ua3, xp3, wa3, ua3); FMA2(ub3, xp3, wb3, ub3);                    \
    }

// packed elementwise dot of 8 pairs -> scalar (lo+hi)
#define PDOT8(res, ua0, ub0, ua1, ub1, ua2, ub2, ua3, ub3,                     \
              va0, vb0, va1, vb1, va2, vb2, va3, vb3)                          \
    {                                                                          \
        u64 t_;                                                                \
        MUL2(t_, ua0, va0); FMA2(t_, ub0, vb0, t_);                            \
        FMA2(t_, ua1, va1, t_); FMA2(t_, ub1, vb1, t_);                        \
        FMA2(t_, ua2, va2, t_); FMA2(t_, ub2, vb2, t_);                        \
        FMA2(t_, ua3, va3, t_); FMA2(t_, ub3, vb3, t_);                        \
        float lo_, hi_;                                                        \
        UNPK2(lo_, hi_, t_);                                                   \
        res = lo_ + hi_;                                                       \
    }

__global__ __launch_bounds__(256, 2)
void convcaps_kernel(const float* __restrict__ x,
                     float* __restrict__ out) {
    extern __shared__ float smem[];
    float* Xs   = smem;
    float* vbuf = smem + 4608;
    float* vcur = smem + 8704;
    float* invd = smem + 9216;
    float* mred = smem + 9248;
    float* nred = smem + 9504;

    const int tid  = threadIdx.x;
    const int lane = tid & 31;     // = C
    const int wp   = tid >> 5;     // warp id, B ≡ wp (mod 8)
    const int pos  = blockIdx.x;   // b*64 + h*8 + w
    const int b    = pos >> 6;
    const int hw   = pos & 63;
    const int h    = hw >> 3;
    const int w    = hw & 7;

    // ---- gather patch poses X[B_=Bcap*9+ki*3+kj][ps] with zero padding ----
    for (int idx = tid; idx < 4608; idx += 256) {
        int B_ = idx >> 4, p = idx & 15;
        int Bcap = B_ / 9;
        int kk = B_ - Bcap * 9;
        int ki = kk / 3, kj = kk - ki * 3;
        int hh = 2 * h + ki - 1, ww = 2 * w + kj - 1;
        float val = 0.f;
        if ((unsigned)hh < 16u && (unsigned)ww < 16u)
            val = x[(((b * 32 + Bcap) * 16 + p) << 8) + (hh << 4) + ww];
        Xs[idx] = val;
    }
    __syncthreads();

    const float4* Xv     = reinterpret_cast<const float4*>(Xs);
    float4*       vbufv  = reinterpret_cast<float4*>(vbuf);
    float4*       vcurv  = reinterpret_cast<float4*>(vcur);
    ulonglong2*   vbufp  = reinterpret_cast<ulonglong2*>(vbuf);
    const ulonglong2* vcurp = reinterpret_cast<const ulonglong2*>(vcur);

    u64 aa0, ab0, aa1, ab1, aa2, ab2, aa3, ab3;

    // ================= PASS A: norms (for max-min) + uniform sum ==========
    {
        float mx = -3.4e38f, mn = 3.4e38f;
        u64 z = 0;
        aa0 = ab0 = aa1 = ab1 = aa2 = ab2 = aa3 = ab3 = z;
        for (int B = wp; B < 288; B += 16) {
            u64 wa0, wb0, wa1, wb1, wa2, wb2, wa3, wb3;
            u64 ya0, yb0, ya1, yb1, ya2, yb2, ya3, yb3;
            LOADW(B,     wa0, wb0, wa1, wb1, wa2, wb2, wa3, wb3)
            LOADW(B + 8, ya0, yb0, ya1, yb1, ya2, yb2, ya3, yb3)
            u64 ua0, ub0, ua1, ub1, ua2, ub2, ua3, ub3;
            u64 za0, zb0, za1, zb1, za2, zb2, za3, zb3;
            COMPUTE_U_P(B,     wa0, wb0, wa1, wb1, wa2, wb2, wa3, wb3,
                               ua0, ub0, ua1, ub1, ua2, ub2, ua3, ub3)
            COMPUTE_U_P(B + 8, ya0, yb0, ya1, yb1, ya2, yb2, ya3, yb3,
                               za0, zb0, za1, zb1, za2, zb2, za3, zb3)
            float sa, sb;
            PDOT8(sa, ua0, ub0, ua1, ub1, ua2, ub2, ua3, ub3,
                      ua0, ub0, ua1, ub1, ua2, ub2, ua3, ub3)
            PDOT8(sb, za0, zb0, za1, zb1, za2, zb2, za3, zb3,
                      za0, zb0, za1, zb1, za2, zb2, za3, zb3)
            float na = __fsqrt_rn(sa + EPSF);
            float nb = __fsqrt_rn(sb + EPSF);
            mx = fmaxf(mx, fmaxf(na, nb));
            mn = fminf(mn, fminf(na, nb));
            ADD2(aa0, aa0, ua0); ADD2(ab0, ab0, ub0);
            ADD2(aa1, aa1, ua1); ADD2(ab1, ab1, ub1);
            ADD2(aa2, aa2, ua2); ADD2(ab2, ab2, ub2);
            ADD2(aa3, aa3, ua3); ADD2(ab3, ab3, ub3);
            ADD2(aa0, aa0, za0); ADD2(ab0, ab0, zb0);
            ADD2(aa1, aa1, za1); ADD2(ab1, ab1, zb1);
            ADD2(aa2, aa2, za2); ADD2(ab2, ab2, zb2);
            ADD2(aa3, aa3, za3); ADD2(ab3, ab3, zb3);
        }
        mred[(wp << 5) + lane] = mx;
        nred[(wp << 5) + lane] = mn;
        int base = ((wp << 5) + lane) << 2;
        ulonglong2 s0; s0.x = aa0; s0.y = ab0; vbufp[base + 0] = s0;
        ulonglong2 s1; s1.x = aa1; s1.y = ab1; vbufp[base + 1] = s1;
        ulonglong2 s2; s2.x = aa2; s2.y = ab2; vbufp[base + 2] = s2;
        ulonglong2 s3; s3.x = aa3; s3.y = ab3; vbufp[base + 3] = s3;
    }
    __syncthreads();
    if (tid < 32) {
        float M = -3.4e38f, m = 3.4e38f;
        #pragma unroll
        for (int k = 0; k < 8; k++) {
            M = fmaxf(M, mred[(k << 5) + tid]);
            m = fminf(m, nred[(k << 5) + tid]);
        }
        invd[tid] = 1.f / (M - m);
    }
    __syncthreads();
    // reduce across warps + squash -> v0
    if (tid < 128) {
        int C = tid >> 2;
        float4 acc = vbufv[tid];
        #pragma unroll
        for (int k = 1; k < 8; k++) {
            float4 t = vbufv[(k << 7) + tid];
            acc.x += t.x; acc.y += t.y; acc.z += t.z; acc.w += t.w;
        }
        float f = invd[C] * (1.f / 32.f);
        acc.x *= f; acc.y *= f; acc.z *= f; acc.w *= f;
        float s = acc.x * acc.x + acc.y * acc.y + acc.z * acc.z + acc.w * acc.w;
        s += __shfl_xor_sync(0xffffffffu, s, 1);
        s += __shfl_xor_sync(0xffffffffu, s, 2);
        float nrm = __fsqrt_rn(s + EPSF);
        float g = 1.f / (1.f + nrm);
        acc.x *= g; acc.y *= g; acc.z *= g; acc.w *= g;
        vcurv[tid] = acc;
    }
    __syncthreads();

    const float invd_c = invd[lane];

    // v0 packed, kept in registers (pass C uses v0+v1 by linearity)
    u64 va0, vb0, va1, vb1, va2, vb2, va3, vb3;
    {
        ulonglong2 t0 = vcurp[(lane << 2) + 0];
        ulonglong2 t1 = vcurp[(lane << 2) + 1];
        ulonglong2 t2 = vcurp[(lane << 2) + 2];
        ulonglong2 t3 = vcurp[(lane << 2) + 3];
        va0 = t0.x; vb0 = t0.y; va1 = t1.x; vb1 = t1.y;
        va2 = t2.x; vb2 = t2.y; va3 = t3.x; vb3 = t3.y;
    }

// Routing pass body: 2-way interleaved (B, B+8), twin shuffle chains.
#define ROUTING_PASS_LOOP                                                      \
    for (int B = wp; B < 288; B += 16) {                                       \
        u64 wa0, wb0, wa1, wb1, wa2, wb2, wa3, wb3;                            \
        u64 ya0, yb0, ya1, yb1, ya2, yb2, ya3, yb3;                            \
        LOADW(B,     wa0, wb0, wa1, wb1, wa2, wb2, wa3, wb3)                   \
        LOADW(B + 8, ya0, yb0, ya1, yb1, ya2, yb2, ya3, yb3)                   \
        u64 ua0, ub0, ua1, ub1, ua2, ub2, ua3, ub3;                            \
        u64 za0, zb0, za1, zb1, za2, zb2, za3, zb3;                            \
        COMPUTE_U_P(B,     wa0, wb0, wa1, wb1, wa2, wb2, wa3, wb3,             \
                           ua0, ub0, ua1, ub1, ua2, ub2, ua3, ub3)             \
        COMPUTE_U_P(B + 8, ya0, yb0, ya1, yb1, ya2, yb2, ya3, yb3,             \
                           za0, zb0, za1, zb1, za2, zb2, za3, zb3)             \
        float dta, dtb;                                                        \
        PDOT8(dta, ua0, ub0, ua1, ub1, ua2, ub2, ua3, ub3,                     \
                   va0, vb0, va1, vb1, va2, vb2, va3, vb3)                     \
        PDOT8(dtb, za0, zb0, za1, zb1, za2, zb2, za3, zb3,                     \
                   va0, vb0, va1, vb1, va2, vb2, va3, vb3)                     \
        float ea = __expf(dta * invd_c);                                       \
        float eb = __expf(dtb * invd_c);                                       \
        float sa = ea, sb = eb;                                                \
        _Pragma("unroll")                                                      \
        for (int o = 16; o > 0; o >>= 1) {                                     \
            sa += __shfl_xor_sync(0xffffffffu, sa, o);                         \
            sb += __shfl_xor_sync(0xffffffffu, sb, o);                         \
        }                                                                      \
        float ca = __fdividef(ea, sa);                                         \
        float cb = __fdividef(eb, sb);                                         \
        u64 caP, cbP;                                                          \
        PACK2(caP, ca); PACK2(cbP, cb);                                        \
        FMA2(aa0, caP, ua0, aa0); FMA2(ab0, caP, ub0, ab0);                    \
        FMA2(aa1, caP, ua1, aa1); FMA2(ab1, caP, ub1, ab1);                    \
        FMA2(aa2, caP, ua2, aa2); FMA2(ab2, caP, ub2, ab2);                    \
        FMA2(aa3, caP, ua3, aa3); FMA2(ab3, caP, ub3, ab3);                    \
        FMA2(aa0, cbP, za0, aa0); FMA2(ab0, cbP, zb0, ab0);                    \
        FMA2(aa1, cbP, za1, aa1); FMA2(ab1, cbP, zb1, ab1);                    \
        FMA2(aa2, cbP, za2, aa2); FMA2(ab2, cbP, zb2, ab2);                    \
        FMA2(aa3, cbP, za3, aa3); FMA2(ab3, cbP, zb3, ab3);                    \
    }

    // ================= PASS B: r1 = u.v0, c1 = softmax_C, accum c1*u ======
    {
        u64 z = 0;
        aa0 = ab0 = aa1 = ab1 = aa2 = ab2 = aa3 = ab3 = z;
        ROUTING_PASS_LOOP
        int base = ((wp << 5) + lane) << 2;
        ulonglong2 s0; s0.x = aa0; s0.y = ab0; vbufp[base + 0] = s0;
        ulonglong2 s1; s1.x = aa1; s1.y = ab1; vbufp[base + 1] = s1;
        ulonglong2 s2; s2.x = aa2; s2.y = ab2; vbufp[base + 2] = s2;
        ulonglong2 s3; s3.x = aa3; s3.y = ab3; vbufp[base + 3] = s3;
    }
    __syncthreads();
    if (tid < 128) {
        int C = tid >> 2;
        float4 acc = vbufv[tid];
        #pragma unroll
        for (int k = 1; k < 8; k++) {
            float4 t = vbufv[(k << 7) + tid];
            acc.x += t.x; acc.y += t.y; acc.z += t.z; acc.w += t.w;
        }
        float f = invd[C];
        acc.x *= f; acc.y *= f; acc.z *= f; acc.w *= f;
        float s = acc.x * acc.x + acc.y * acc.y + acc.z * acc.z + acc.w * acc.w;
        s += __shfl_xor_sync(0xffffffffu, s, 1);
        s += __shfl_xor_sync(0xffffffffu, s, 2);
        float nrm = __fsqrt_rn(s + EPSF);
        float g = 1.f / (1.f + nrm);
        acc.x *= g; acc.y *= g; acc.z *= g; acc.w *= g;
        vcurv[tid] = acc;   // v1
    }
    __syncthreads();

    // vl = v0 + v1 (linearity: r2 = r1 + u.v1*invd = invd * u.(v0+v1))
    {
        ulonglong2 t0 = vcurp[(lane << 2) + 0];
        ulonglong2 t1 = vcurp[(lane << 2) + 1];
        ulonglong2 t2 = vcurp[(lane << 2) + 2];
        ulonglong2 t3 = vcurp[(lane << 2) + 3];
        ADD2(va0, va0, t0.x); ADD2(vb0, vb0, t0.y);
        ADD2(va1, va1, t1.x); ADD2(vb1, vb1, t1.y);
        ADD2(va2, va2, t2.x); ADD2(vb2, vb2, t2.y);
        ADD2(va3, va3, t3.x); ADD2(vb3, vb3, t3.y);
    }

    // ================= PASS C: r2 = invd*u.(v0+v1), c2, accum, output ======
    {
        u64 z = 0;
        aa0 = ab0 = aa1 = ab1 = aa2 = ab2 = aa3 = ab3 = z;
        ROUTING_PASS_LOOP
        int base = ((wp << 5) + lane) << 2;
        ulonglong2 s0; s0.x = aa0; s0.y = ab0; vbufp[base + 0] = s0;
        ulonglong2 s1; s1.x = aa1; s1.y = ab1; vbufp[base + 1] = s1;
        ulonglong2 s2; s2.x = aa2; s2.y = ab2; vbufp[base + 2] = s2;
        ulonglong2 s3; s3.x = aa3; s3.y = ab3; vbufp[base + 3] = s3;
    }
    __syncthreads();
    if (tid < 128) {
        int C = tid >> 2, q = tid & 3;
        float4 acc = vbufv[tid];
        #pragma unroll
        for (int k = 1; k < 8; k++) {
            float4 t = vbufv[(k << 7) + tid];
            acc.x += t.x; acc.y += t.y; acc.z += t.z; acc.w += t.w;
        }
        float f = invd[C];
        acc.x *= f; acc.y *= f; acc.z *= f; acc.w *= f;
        float s = acc.x * acc.x + acc.y * acc.y + acc.z * acc.z + acc.w * acc.w;
        s += __shfl_xor_sync(0xffffffffu, s, 1);
        s += __shfl_xor_sync(0xffffffffu, s, 2);
        float nrm = __fsqrt_rn(s + EPSF);
        float g = 1.f / (1.f + nrm);
        acc.x *= g; acc.y *= g; acc.z *= g; acc.w *= g;   // v2 (p_out)
        float s2 = acc.x * acc.x + acc.y * acc.y + acc.z * acc.z + acc.w * acc.w;
        s2 += __shfl_xor_sync(0xffffffffu, s2, 1);
        s2 += __shfl_xor_sync(0xffffffffu, s2, 2);
        float aout = __fsqrt_rn(s2 + EPSF);               // a_out = safe_norm(v2)
        int basep = (((b * 32 + C) * 16 + (q << 2)) << 6) + hw;
        out[basep]       = acc.x;
        out[basep + 64]  = acc.y;
        out[basep + 128] = acc.z;
        out[basep + 192] = acc.w;
        if (q == 0)
            out[AOUT_BASE + ((b * 32 + C) << 6) + hw] = aout;
    }
}

extern "C" void kernel_launch(void* const* d_in, const int* in_sizes, int n_in,
                              void* d_out, int out_size) {
    (void)out_size;
    // Resolve inputs BY SIZE — immune to metadata ordering.
    const float* x  = nullptr;
    const float* Wg = nullptr;
    for (int i = 0; i < n_in; i++) {
        if (in_sizes[i] == 524288)      x  = (const float*)d_in[i];
        else if (in_sizes[i] == 147456) Wg = (const float*)d_in[i];
    }
    float* out = (float*)d_out;

    transpose_W_kernel<<<(288 * 16 * 32 + 255) / 256, 256>>>(Wg);

    const size_t smem_bytes = SMEM_FLOATS * sizeof(float);
    cudaFuncSetAttribute(convcaps_kernel,
                         cudaFuncAttributeMaxDynamicSharedMemorySize,
                         (int)smem_bytes);
    convcaps_kernel<<<256, 256, smem_bytes>>>(x, out);
}